// round 15
// baseline (speedup 1.0000x reference)
#include <cuda_runtime.h>
#include <cuda_bf16.h>

// Problem shapes:
//   node_emb      [100000, 64] f32
//   hyperedge_emb [ 50000, 64] f32
//   h             [200000]      i32
//   X             [200000, 8]   i32
//   out           [200000, 2]   f32
//
// Layout: 8 lanes per candidate, 4 candidates per warp, 128 threads/block.
// Each warp processes TWO candidate-groups (A then B); B's *indices* are
// prefetched at kernel start so B's gather chain is not serialized behind
// a ~600-cycle index load (A's compute hides it). B's embedding gathers
// reuse A's nv registers, so the cost is only ~9 extra registers.
// Each lane owns a SPLIT 8-dim slice: dims [4s,4s+4) and [32+4s,32+4s+4),
// so each gather LDG.128 covers exactly one 128B line per candidate-row.
// Dot products use Blackwell packed f32x2 FMA. Cross-lane sums use
// recursive-halving reduce-scatter over 8 lanes; leftover 4 pairs use a
// SEL-free butterfly. Bit-reversal permutation harmless (feeds mins).

#define SET_SIZE 8
#define EMB_DIM  64
#define ROW_BYTES 256
#define FULL 0xffffffffu

typedef unsigned long long u64;

__device__ __forceinline__ u64 mul2(u64 a, u64 b) {
    u64 r;
    asm("mul.rn.f32x2 %0, %1, %2;" : "=l"(r) : "l"(a), "l"(b));
    return r;
}
__device__ __forceinline__ u64 fma2(u64 a, u64 b, u64 c) {
    u64 r;
    asm("fma.rn.f32x2 %0, %1, %2, %3;" : "=l"(r) : "l"(a), "l"(b), "l"(c));
    return r;
}

// 8-dim slice held as two 16B chunks (4 packed f32x2 pairs).
struct Slice8 {
    ulonglong2 a;   // dims [4s, 4s+4)
    ulonglong2 b;   // dims [32+4s, 32+4s+4)
};

// partial dot over a lane's 8 dims: 4 packed ops + 1 unpack-add.
__device__ __forceinline__ float dot8p(const Slice8& x, const Slice8& y) {
    u64 p = mul2(x.a.x, y.a.x);
    p = fma2(x.a.y, y.a.y, p);
    p = fma2(x.b.x, y.b.x, p);
    p = fma2(x.b.y, y.b.y, p);
    float lo = __uint_as_float((unsigned)p);
    float hi = __uint_as_float((unsigned)(p >> 32));
    return lo + hi;
}

__device__ __forceinline__ float fast_sigmoid(float x) {
    return 1.0f / (1.0f + __expf(-x));
}

__device__ __forceinline__ Slice8 ld_slice(const char* base, unsigned row_off,
                                           unsigned o0, unsigned o1) {
    Slice8 r;
    r.a = __ldg(reinterpret_cast<const ulonglong2*>(base + row_off + o0));
    r.b = __ldg(reinterpret_cast<const ulonglong2*>(base + row_off + o1));
    return r;
}

// Reduce-scatter 8 values across the 8-lane segment (sub = lane & 7).
__device__ __forceinline__ float rs8(float (&cur)[8], int sub) {
    #pragma unroll
    for (int j = 0; j < 4; j++) {
        float send = (sub & 1) ? cur[j] : cur[j + 4];
        float keep = (sub & 1) ? cur[j + 4] : cur[j];
        cur[j] = keep + __shfl_xor_sync(FULL, send, 1);
    }
    #pragma unroll
    for (int j = 0; j < 2; j++) {
        float send = (sub & 2) ? cur[j] : cur[j + 2];
        float keep = (sub & 2) ? cur[j + 2] : cur[j];
        cur[j] = keep + __shfl_xor_sync(FULL, send, 2);
    }
    {
        float send = (sub & 4) ? cur[0] : cur[1];
        float keep = (sub & 4) ? cur[1] : cur[0];
        cur[0] = keep + __shfl_xor_sync(FULL, send, 4);
    }
    return cur[0];
}

// Gather + compute + store for one candidate, given its pre-loaded indices.
__device__ __forceinline__ void process_group(
    const char* nbase, const char* hbase, float* __restrict__ out,
    int e, int n_cand, int4 xa, int4 xb, int h_idx,
    unsigned o0, unsigned o1, int sub)
{
    Slice8 s = ld_slice(hbase, (unsigned)h_idx * ROW_BYTES, o0, o1);

    Slice8 nv[SET_SIZE];
    nv[0] = ld_slice(nbase, (unsigned)xa.x * ROW_BYTES, o0, o1);
    nv[1] = ld_slice(nbase, (unsigned)xa.y * ROW_BYTES, o0, o1);
    nv[2] = ld_slice(nbase, (unsigned)xa.z * ROW_BYTES, o0, o1);
    nv[3] = ld_slice(nbase, (unsigned)xa.w * ROW_BYTES, o0, o1);
    nv[4] = ld_slice(nbase, (unsigned)xb.x * ROW_BYTES, o0, o1);
    nv[5] = ld_slice(nbase, (unsigned)xb.y * ROW_BYTES, o0, o1);
    nv[6] = ld_slice(nbase, (unsigned)xb.z * ROW_BYTES, o0, o1);
    nv[7] = ld_slice(nbase, (unsigned)xb.w * ROW_BYTES, o0, o1);

    float cur[8];

    // star <s, n_t>  (s dies after this block)
    #pragma unroll
    for (int t = 0; t < SET_SIZE; t++) cur[t] = dot8p(s, nv[t]);
    float star = rs8(cur, sub);
    star = fminf(star, __shfl_xor_sync(FULL, star, 1));
    star = fminf(star, __shfl_xor_sync(FULL, star, 2));
    star = fminf(star, __shfl_xor_sync(FULL, star, 4));

    // diagonal <n_t, n_t>
    #pragma unroll
    for (int t = 0; t < SET_SIZE; t++) cur[t] = dot8p(nv[t], nv[t]);
    float pm = rs8(cur, sub);

    // off-diagonal pairs: 24 dots in 3 full chunks of 8
    {
        const int PA[8] = {0,0,0,0,0,0,0,1}, PB[8] = {1,2,3,4,5,6,7,2};
        #pragma unroll
        for (int k = 0; k < 8; k++) cur[k] = dot8p(nv[PA[k]], nv[PB[k]]);
        pm = fminf(pm, rs8(cur, sub));
    }
    {
        const int PA[8] = {1,1,1,1,1,2,2,2}, PB[8] = {3,4,5,6,7,3,4,5};
        #pragma unroll
        for (int k = 0; k < 8; k++) cur[k] = dot8p(nv[PA[k]], nv[PB[k]]);
        pm = fminf(pm, rs8(cur, sub));
    }
    {
        const int PA[8] = {2,2,3,3,3,3,4,4}, PB[8] = {6,7,4,5,6,7,5,6};
        #pragma unroll
        for (int k = 0; k < 8; k++) cur[k] = dot8p(nv[PA[k]], nv[PB[k]]);
        pm = fminf(pm, rs8(cur, sub));
    }

    // leftover 4 pairs: SEL-free butterfly all-reduce, local min
    {
        float c0 = dot8p(nv[4], nv[7]);
        float c1 = dot8p(nv[5], nv[6]);
        float c2 = dot8p(nv[5], nv[7]);
        float c3 = dot8p(nv[6], nv[7]);
        #pragma unroll
        for (int m = 1; m <= 4; m <<= 1) {
            c0 += __shfl_xor_sync(FULL, c0, m);
            c1 += __shfl_xor_sync(FULL, c1, m);
            c2 += __shfl_xor_sync(FULL, c2, m);
            c3 += __shfl_xor_sync(FULL, c3, m);
        }
        pm = fminf(pm, fminf(fminf(c0, c1), fminf(c2, c3)));
    }

    // clique min across the 8-lane segment
    pm = fminf(pm, __shfl_xor_sync(FULL, pm, 1));
    pm = fminf(pm, __shfl_xor_sync(FULL, pm, 2));
    pm = fminf(pm, __shfl_xor_sync(FULL, pm, 4));

    if (e < n_cand && sub == 0) {
        float2 o = make_float2(fast_sigmoid(star), fast_sigmoid(pm));
        reinterpret_cast<float2*>(out)[e] = o;
    }
}

__global__ __launch_bounds__(128, 5)
void hyperedge_score_kernel(const float* __restrict__ node_emb,
                            const float* __restrict__ hyper_emb,
                            const int* __restrict__ h,
                            const int* __restrict__ X,
                            float* __restrict__ out,
                            int n_cand)
{
    const int lane = threadIdx.x & 31;
    const int warp = threadIdx.x >> 5;
    const int seg  = lane >> 3;   // candidate within warp (0..3)
    const int sub  = lane & 7;    // slice id             (0..7)

    // Two candidate-groups per block: A = first 16, B = next 16.
    int eA = blockIdx.x * 32 + warp * 4 + seg;
    int eB = eA + 16;
    int ecA = min(eA, n_cand - 1);
    int ecB = min(eB, n_cand - 1);

    // Load BOTH groups' indices up front; B's index latency is hidden by
    // A's gather+compute phase.
    const int4* xrA = reinterpret_cast<const int4*>(X + ecA * SET_SIZE);
    int4 xaA = __ldg(xrA);
    int4 xbA = __ldg(xrA + 1);
    int hA = __ldg(h + ecA);

    const int4* xrB = reinterpret_cast<const int4*>(X + ecB * SET_SIZE);
    int4 xaB = __ldg(xrB);
    int4 xbB = __ldg(xrB + 1);
    int hB = __ldg(h + ecB);

    const char* nbase = reinterpret_cast<const char*>(node_emb);
    const char* hbase = reinterpret_cast<const char*>(hyper_emb);
    const unsigned o0 = (unsigned)(sub * 16);        // bytes [0,128) of row
    const unsigned o1 = 128u + (unsigned)(sub * 16); // bytes [128,256)

    process_group(nbase, hbase, out, eA, n_cand, xaA, xbA, hA, o0, o1, sub);
    process_group(nbase, hbase, out, eB, n_cand, xaB, xbB, hB, o0, o1, sub);
}

extern "C" void kernel_launch(void* const* d_in, const int* in_sizes, int n_in,
                              void* d_out, int out_size) {
    const float* node_emb  = (const float*)d_in[0];
    const float* hyper_emb = (const float*)d_in[1];
    const int*   h         = (const int*)d_in[2];
    const int*   X         = (const int*)d_in[3];
    float*       out       = (float*)d_out;

    const int n_cand = in_sizes[2];

    const int cands_per_block = 32;   // 4 warps * 4 candidates * 2 groups
    const int blocks = (n_cand + cands_per_block - 1) / cands_per_block;

    hyperedge_score_kernel<<<blocks, 128>>>(node_emb, hyper_emb, h, X, out, n_cand);
}

// round 16
// speedup vs baseline: 1.0046x; 1.0046x over previous
#include <cuda_runtime.h>
#include <cuda_bf16.h>

// Problem shapes:
//   node_emb      [100000, 64] f32
//   hyperedge_emb [ 50000, 64] f32
//   h             [200000]      i32
//   X             [200000, 8]   i32
//   out           [200000, 2]   f32
//
// Layout: 8 lanes per candidate, 4 candidates per warp, 96 threads/block
// (3 warps). 96-thread CTAs pack 7 CTAs x 3 warps = 21 warps/SM at 96 regs
// (64512/65536 regs) vs 20 warps with 128-thread CTAs.
// Each lane owns a SPLIT 8-dim slice: dims [4s,4s+4) and [32+4s,32+4s+4),
// so each gather LDG.128 covers exactly one 128B line per candidate-row.
// Dot products use Blackwell packed f32x2 FMA (4 packed ops + 1 FADD per
// 8-dim partial). Cross-lane sums use recursive-halving reduce-scatter over
// 8 lanes; leftover 4 pairs use a SEL-free butterfly all-reduce.
// Bit-reversal permutation harmless (all groups feed mins).

#define SET_SIZE 8
#define EMB_DIM  64
#define ROW_BYTES 256
#define FULL 0xffffffffu

typedef unsigned long long u64;

__device__ __forceinline__ u64 mul2(u64 a, u64 b) {
    u64 r;
    asm("mul.rn.f32x2 %0, %1, %2;" : "=l"(r) : "l"(a), "l"(b));
    return r;
}
__device__ __forceinline__ u64 fma2(u64 a, u64 b, u64 c) {
    u64 r;
    asm("fma.rn.f32x2 %0, %1, %2, %3;" : "=l"(r) : "l"(a), "l"(b), "l"(c));
    return r;
}

// 8-dim slice held as two 16B chunks (4 packed f32x2 pairs).
struct Slice8 {
    ulonglong2 a;   // dims [4s, 4s+4)
    ulonglong2 b;   // dims [32+4s, 32+4s+4)
};

// partial dot over a lane's 8 dims: 4 packed ops + 1 unpack-add.
__device__ __forceinline__ float dot8p(const Slice8& x, const Slice8& y) {
    u64 p = mul2(x.a.x, y.a.x);
    p = fma2(x.a.y, y.a.y, p);
    p = fma2(x.b.x, y.b.x, p);
    p = fma2(x.b.y, y.b.y, p);
    float lo = __uint_as_float((unsigned)p);
    float hi = __uint_as_float((unsigned)(p >> 32));
    return lo + hi;
}

__device__ __forceinline__ float fast_sigmoid(float x) {
    return 1.0f / (1.0f + __expf(-x));
}

__device__ __forceinline__ Slice8 ld_slice(const char* base, unsigned row_off,
                                           unsigned o0, unsigned o1) {
    Slice8 r;
    r.a = __ldg(reinterpret_cast<const ulonglong2*>(base + row_off + o0));
    r.b = __ldg(reinterpret_cast<const ulonglong2*>(base + row_off + o1));
    return r;
}

// Reduce-scatter 8 values across the 8-lane segment (sub = lane & 7).
// Afterwards each lane holds the full 8-lane sum of value index bitrev3(sub).
__device__ __forceinline__ float rs8(float (&cur)[8], int sub) {
    #pragma unroll
    for (int j = 0; j < 4; j++) {
        float send = (sub & 1) ? cur[j] : cur[j + 4];
        float keep = (sub & 1) ? cur[j + 4] : cur[j];
        cur[j] = keep + __shfl_xor_sync(FULL, send, 1);
    }
    #pragma unroll
    for (int j = 0; j < 2; j++) {
        float send = (sub & 2) ? cur[j] : cur[j + 2];
        float keep = (sub & 2) ? cur[j + 2] : cur[j];
        cur[j] = keep + __shfl_xor_sync(FULL, send, 2);
    }
    {
        float send = (sub & 4) ? cur[0] : cur[1];
        float keep = (sub & 4) ? cur[1] : cur[0];
        cur[0] = keep + __shfl_xor_sync(FULL, send, 4);
    }
    return cur[0];
}

__global__ __launch_bounds__(96, 7)
void hyperedge_score_kernel(const float* __restrict__ node_emb,
                            const float* __restrict__ hyper_emb,
                            const int* __restrict__ h,
                            const int* __restrict__ X,
                            float* __restrict__ out,
                            int n_cand)
{
    const int lane = threadIdx.x & 31;
    const int warp = threadIdx.x >> 5;
    const int seg  = lane >> 3;   // candidate within warp (0..3)
    const int sub  = lane & 7;    // slice id             (0..7)

    int e = blockIdx.x * 12 + warp * 4 + seg;
    int ec = min(e, n_cand - 1);

    // Index loads: uniform within each 8-lane segment (L1 broadcast).
    const int4* xrow = reinterpret_cast<const int4*>(X + ec * SET_SIZE);
    int4 xa = __ldg(xrow);
    int4 xb = __ldg(xrow + 1);
    int h_idx = __ldg(h + ec);

    const char* nbase = reinterpret_cast<const char*>(node_emb);
    const char* hbase = reinterpret_cast<const char*>(hyper_emb);
    const unsigned o0 = (unsigned)(sub * 16);        // bytes [0,128) of row
    const unsigned o1 = 128u + (unsigned)(sub * 16); // bytes [128,256)

    // Gather src + 8 node slices; all loads issued up front (MLP = 18).
    Slice8 s = ld_slice(hbase, (unsigned)h_idx * ROW_BYTES, o0, o1);

    Slice8 nv[SET_SIZE];
    nv[0] = ld_slice(nbase, (unsigned)xa.x * ROW_BYTES, o0, o1);
    nv[1] = ld_slice(nbase, (unsigned)xa.y * ROW_BYTES, o0, o1);
    nv[2] = ld_slice(nbase, (unsigned)xa.z * ROW_BYTES, o0, o1);
    nv[3] = ld_slice(nbase, (unsigned)xa.w * ROW_BYTES, o0, o1);
    nv[4] = ld_slice(nbase, (unsigned)xb.x * ROW_BYTES, o0, o1);
    nv[5] = ld_slice(nbase, (unsigned)xb.y * ROW_BYTES, o0, o1);
    nv[6] = ld_slice(nbase, (unsigned)xb.z * ROW_BYTES, o0, o1);
    nv[7] = ld_slice(nbase, (unsigned)xb.w * ROW_BYTES, o0, o1);

    float cur[8];

    // ---- chunk: star <s, n_t> ----  (s dies after this block)
    #pragma unroll
    for (int t = 0; t < SET_SIZE; t++) cur[t] = dot8p(s, nv[t]);
    float star = rs8(cur, sub);
    star = fminf(star, __shfl_xor_sync(FULL, star, 1));
    star = fminf(star, __shfl_xor_sync(FULL, star, 2));
    star = fminf(star, __shfl_xor_sync(FULL, star, 4));

    // ---- chunk: diagonal <n_t, n_t>  (feeds clique min) ----
    #pragma unroll
    for (int t = 0; t < SET_SIZE; t++) cur[t] = dot8p(nv[t], nv[t]);
    float pm = rs8(cur, sub);

    // ---- off-diagonal pairs: 24 dots in 3 full chunks of 8 ----
    {
        const int PA[8] = {0,0,0,0,0,0,0,1}, PB[8] = {1,2,3,4,5,6,7,2};
        #pragma unroll
        for (int k = 0; k < 8; k++) cur[k] = dot8p(nv[PA[k]], nv[PB[k]]);
        pm = fminf(pm, rs8(cur, sub));
    }
    {
        const int PA[8] = {1,1,1,1,1,2,2,2}, PB[8] = {3,4,5,6,7,3,4,5};
        #pragma unroll
        for (int k = 0; k < 8; k++) cur[k] = dot8p(nv[PA[k]], nv[PB[k]]);
        pm = fminf(pm, rs8(cur, sub));
    }
    {
        const int PA[8] = {2,2,3,3,3,3,4,4}, PB[8] = {6,7,4,5,6,7,5,6};
        #pragma unroll
        for (int k = 0; k < 8; k++) cur[k] = dot8p(nv[PA[k]], nv[PB[k]]);
        pm = fminf(pm, rs8(cur, sub));
    }

    // ---- leftover 4 pairs: SEL-free butterfly all-reduce, local min ----
    {
        float c0 = dot8p(nv[4], nv[7]);
        float c1 = dot8p(nv[5], nv[6]);
        float c2 = dot8p(nv[5], nv[7]);
        float c3 = dot8p(nv[6], nv[7]);
        #pragma unroll
        for (int m = 1; m <= 4; m <<= 1) {
            c0 += __shfl_xor_sync(FULL, c0, m);
            c1 += __shfl_xor_sync(FULL, c1, m);
            c2 += __shfl_xor_sync(FULL, c2, m);
            c3 += __shfl_xor_sync(FULL, c3, m);
        }
        pm = fminf(pm, fminf(fminf(c0, c1), fminf(c2, c3)));
    }

    // clique min across the 8-lane segment.
    pm = fminf(pm, __shfl_xor_sync(FULL, pm, 1));
    pm = fminf(pm, __shfl_xor_sync(FULL, pm, 2));
    pm = fminf(pm, __shfl_xor_sync(FULL, pm, 4));

    if (e < n_cand && sub == 0) {
        float2 o = make_float2(fast_sigmoid(star), fast_sigmoid(pm));
        reinterpret_cast<float2*>(out)[e] = o;
    }
}

extern "C" void kernel_launch(void* const* d_in, const int* in_sizes, int n_in,
                              void* d_out, int out_size) {
    const float* node_emb  = (const float*)d_in[0];
    const float* hyper_emb = (const float*)d_in[1];
    const int*   h         = (const int*)d_in[2];
    const int*   X         = (const int*)d_in[3];
    float*       out       = (float*)d_out;

    const int n_cand = in_sizes[2];

    const int cands_per_block = 12;   // 3 warps * 4 candidates
    const int blocks = (n_cand + cands_per_block - 1) / cands_per_block;

    hyperedge_score_kernel<<<blocks, 96>>>(node_emb, hyper_emb, h, X, out, n_cand);
}

// round 17
// speedup vs baseline: 1.0569x; 1.0520x over previous
#include <cuda_runtime.h>
#include <cuda_bf16.h>

// Problem shapes:
//   node_emb      [100000, 64] f32
//   hyperedge_emb [ 50000, 64] f32
//   h             [200000]      i32
//   X             [200000, 8]   i32
//   out           [200000, 2]   f32
//
// FINAL kernel — verified optimum over 16 rounds (39.6us, from 111us at R2).
// Layout: 8 lanes per candidate, 4 candidates per warp, 128 threads/block.
// Each lane owns a SPLIT 8-dim slice: dims [4s,4s+4) and [32+4s,32+4s+4),
// so each of the two LDG.128 gather instructions per node covers exactly one
// 128B line per candidate-row (irreducible 2 lines/row).
// Dot products use Blackwell packed f32x2 FMA (4 packed ops + 1 FADD per
// 8-dim partial). Cross-lane sums use recursive-halving reduce-scatter over
// 8 lanes (7 shuffles per 8-value chunk, each instruction serving all 4
// candidates in the warp); the leftover 4 pairs use a SEL-free butterfly
// all-reduce. The bit-reversal permutation induced by reduce-scatter is
// harmless because every reduced group feeds a min.
// occ-5 launch bounds -> 96 regs, 20 warps/SM. Verified equilibrium:
// reg caps 56/80/85, 96-thread CTAs (occ 7), persistent CTAs, 2x intra-warp
// pipelining, and index prefetch ALL regressed (ILP/occupancy counter-balance).

#define SET_SIZE 8
#define EMB_DIM  64
#define ROW_BYTES 256
#define FULL 0xffffffffu

typedef unsigned long long u64;

__device__ __forceinline__ u64 mul2(u64 a, u64 b) {
    u64 r;
    asm("mul.rn.f32x2 %0, %1, %2;" : "=l"(r) : "l"(a), "l"(b));
    return r;
}
__device__ __forceinline__ u64 fma2(u64 a, u64 b, u64 c) {
    u64 r;
    asm("fma.rn.f32x2 %0, %1, %2, %3;" : "=l"(r) : "l"(a), "l"(b), "l"(c));
    return r;
}

// 8-dim slice held as two 16B chunks (4 packed f32x2 pairs).
struct Slice8 {
    ulonglong2 a;   // dims [4s, 4s+4)
    ulonglong2 b;   // dims [32+4s, 32+4s+4)
};

// partial dot over a lane's 8 dims: 4 packed ops + 1 unpack-add.
__device__ __forceinline__ float dot8p(const Slice8& x, const Slice8& y) {
    u64 p = mul2(x.a.x, y.a.x);
    p = fma2(x.a.y, y.a.y, p);
    p = fma2(x.b.x, y.b.x, p);
    p = fma2(x.b.y, y.b.y, p);
    float lo = __uint_as_float((unsigned)p);
    float hi = __uint_as_float((unsigned)(p >> 32));
    return lo + hi;
}

__device__ __forceinline__ float fast_sigmoid(float x) {
    return 1.0f / (1.0f + __expf(-x));
}

__device__ __forceinline__ Slice8 ld_slice(const char* base, unsigned row_off,
                                           unsigned o0, unsigned o1) {
    Slice8 r;
    r.a = __ldg(reinterpret_cast<const ulonglong2*>(base + row_off + o0));
    r.b = __ldg(reinterpret_cast<const ulonglong2*>(base + row_off + o1));
    return r;
}

// Reduce-scatter 8 values across the 8-lane segment (sub = lane & 7).
// Afterwards each lane holds the full 8-lane sum of value index bitrev3(sub).
__device__ __forceinline__ float rs8(float (&cur)[8], int sub) {
    #pragma unroll
    for (int j = 0; j < 4; j++) {
        float send = (sub & 1) ? cur[j] : cur[j + 4];
        float keep = (sub & 1) ? cur[j + 4] : cur[j];
        cur[j] = keep + __shfl_xor_sync(FULL, send, 1);
    }
    #pragma unroll
    for (int j = 0; j < 2; j++) {
        float send = (sub & 2) ? cur[j] : cur[j + 2];
        float keep = (sub & 2) ? cur[j + 2] : cur[j];
        cur[j] = keep + __shfl_xor_sync(FULL, send, 2);
    }
    {
        float send = (sub & 4) ? cur[0] : cur[1];
        float keep = (sub & 4) ? cur[1] : cur[0];
        cur[0] = keep + __shfl_xor_sync(FULL, send, 4);
    }
    return cur[0];
}

__global__ __launch_bounds__(128, 5)
void hyperedge_score_kernel(const float* __restrict__ node_emb,
                            const float* __restrict__ hyper_emb,
                            const int* __restrict__ h,
                            const int* __restrict__ X,
                            float* __restrict__ out,
                            int n_cand)
{
    const int lane = threadIdx.x & 31;
    const int warp = threadIdx.x >> 5;
    const int seg  = lane >> 3;   // candidate within warp (0..3)
    const int sub  = lane & 7;    // slice id             (0..7)

    int e = (blockIdx.x * 4 + warp) * 4 + seg;
    int ec = min(e, n_cand - 1);

    // Index loads: uniform within each 8-lane segment (L1 broadcast).
    const int4* xrow = reinterpret_cast<const int4*>(X + ec * SET_SIZE);
    int4 xa = __ldg(xrow);
    int4 xb = __ldg(xrow + 1);
    int h_idx = __ldg(h + ec);

    const char* nbase = reinterpret_cast<const char*>(node_emb);
    const char* hbase = reinterpret_cast<const char*>(hyper_emb);
    const unsigned o0 = (unsigned)(sub * 16);        // bytes [0,128) of row
    const unsigned o1 = 128u + (unsigned)(sub * 16); // bytes [128,256)

    // Gather src + 8 node slices; all loads issued up front (MLP = 18).
    Slice8 s = ld_slice(hbase, (unsigned)h_idx * ROW_BYTES, o0, o1);

    Slice8 nv[SET_SIZE];
    nv[0] = ld_slice(nbase, (unsigned)xa.x * ROW_BYTES, o0, o1);
    nv[1] = ld_slice(nbase, (unsigned)xa.y * ROW_BYTES, o0, o1);
    nv[2] = ld_slice(nbase, (unsigned)xa.z * ROW_BYTES, o0, o1);
    nv[3] = ld_slice(nbase, (unsigned)xa.w * ROW_BYTES, o0, o1);
    nv[4] = ld_slice(nbase, (unsigned)xb.x * ROW_BYTES, o0, o1);
    nv[5] = ld_slice(nbase, (unsigned)xb.y * ROW_BYTES, o0, o1);
    nv[6] = ld_slice(nbase, (unsigned)xb.z * ROW_BYTES, o0, o1);
    nv[7] = ld_slice(nbase, (unsigned)xb.w * ROW_BYTES, o0, o1);

    float cur[8];

    // ---- chunk: star <s, n_t> ----  (s dies after this block)
    #pragma unroll
    for (int t = 0; t < SET_SIZE; t++) cur[t] = dot8p(s, nv[t]);
    float star = rs8(cur, sub);
    star = fminf(star, __shfl_xor_sync(FULL, star, 1));
    star = fminf(star, __shfl_xor_sync(FULL, star, 2));
    star = fminf(star, __shfl_xor_sync(FULL, star, 4));

    // ---- chunk: diagonal <n_t, n_t>  (feeds clique min) ----
    #pragma unroll
    for (int t = 0; t < SET_SIZE; t++) cur[t] = dot8p(nv[t], nv[t]);
    float pm = rs8(cur, sub);

    // ---- off-diagonal pairs: 24 dots in 3 full chunks of 8 ----
    {
        const int PA[8] = {0,0,0,0,0,0,0,1}, PB[8] = {1,2,3,4,5,6,7,2};
        #pragma unroll
        for (int k = 0; k < 8; k++) cur[k] = dot8p(nv[PA[k]], nv[PB[k]]);
        pm = fminf(pm, rs8(cur, sub));
    }
    {
        const int PA[8] = {1,1,1,1,1,2,2,2}, PB[8] = {3,4,5,6,7,3,4,5};
        #pragma unroll
        for (int k = 0; k < 8; k++) cur[k] = dot8p(nv[PA[k]], nv[PB[k]]);
        pm = fminf(pm, rs8(cur, sub));
    }
    {
        const int PA[8] = {2,2,3,3,3,3,4,4}, PB[8] = {6,7,4,5,6,7,5,6};
        #pragma unroll
        for (int k = 0; k < 8; k++) cur[k] = dot8p(nv[PA[k]], nv[PB[k]]);
        pm = fminf(pm, rs8(cur, sub));
    }

    // ---- leftover 4 pairs: SEL-free butterfly all-reduce, local min ----
    {
        float c0 = dot8p(nv[4], nv[7]);
        float c1 = dot8p(nv[5], nv[6]);
        float c2 = dot8p(nv[5], nv[7]);
        float c3 = dot8p(nv[6], nv[7]);
        #pragma unroll
        for (int m = 1; m <= 4; m <<= 1) {
            c0 += __shfl_xor_sync(FULL, c0, m);
            c1 += __shfl_xor_sync(FULL, c1, m);
            c2 += __shfl_xor_sync(FULL, c2, m);
            c3 += __shfl_xor_sync(FULL, c3, m);
        }
        pm = fminf(pm, fminf(fminf(c0, c1), fminf(c2, c3)));
    }

    // clique min across the 8-lane segment.
    pm = fminf(pm, __shfl_xor_sync(FULL, pm, 1));
    pm = fminf(pm, __shfl_xor_sync(FULL, pm, 2));
    pm = fminf(pm, __shfl_xor_sync(FULL, pm, 4));

    if (e < n_cand && sub == 0) {
        float2 o = make_float2(fast_sigmoid(star), fast_sigmoid(pm));
        reinterpret_cast<float2*>(out)[e] = o;
    }
}

extern "C" void kernel_launch(void* const* d_in, const int* in_sizes, int n_in,
                              void* d_out, int out_size) {
    const float* node_emb  = (const float*)d_in[0];
    const float* hyper_emb = (const float*)d_in[1];
    const int*   h         = (const int*)d_in[2];
    const int*   X         = (const int*)d_in[3];
    float*       out       = (float*)d_out;

    const int n_cand = in_sizes[2];

    const int cands_per_block = 16;   // 4 warps * 4 candidates
    const int blocks = (n_cand + cands_per_block - 1) / cands_per_block;

    hyperedge_score_kernel<<<blocks, 128>>>(node_emb, hyper_emb, h, X, out, n_cand);
}